// round 13
// baseline (speedup 1.0000x reference)
#include <cuda_runtime.h>
#include <cuda_bf16.h>
#include <cstdint>
#include <cstddef>

// ---------------------------------------------------------------------------
// TTLinear. Phase A: 3 big tf32 tensor-core GEMMs. Phase B: one persistent
// kernel (256 thr/block, 1 block/SM), 128 sequential SGD steps, 5 barriers.
// R13 = R11 design, implementation rewritten: no lambdas, single sync per
// k-slab (entry-guard + double-buffer), lower code complexity. Fused full-K
// 16x32 tiles with intra-block warp-group split-K + fused epilogues; no
// partial buffers. R6' split-tf32 (near-fp32); gradient GEMMs tf32; S10 fp32.
// ---------------------------------------------------------------------------

constexpr int T_  = 128;
constexpr int NB  = 256;
constexpr int DD  = 1024;
constexpr int HH  = 1024;
constexpr int H4  = 256;
constexpr int NH  = NB * HH;    // 262144
constexpr int MN  = NB * H4;    // 65536
constexpr float LR = 1e-3f;
constexpr float C2 = 2.0f / (float)(NB * HH);

constexpr int SL   = 76;        // padded smem row stride for K=256 tiles
constexpr int SLAB = 16 * SL;

// ------------------------- device scratch ----------------------------------
__device__ float g_Z[(size_t)T_ * NH];
__device__ float g_Y[(size_t)T_ * NH];
__device__ float g_Q[(size_t)T_ * NH];
__device__ float g_W1[H4 * HH];
__device__ float g_b1[H4];
__device__ float g_W2[HH * H4];
__device__ float g_b2[HH];
__device__ float g_a[MN];
__device__ float g_h[MN];
__device__ float g_h2[MN];
__device__ float g_da[MN];
__device__ float g_dr[NB * HH];

__device__ __align__(128) unsigned g_cnt = 0;
__device__ __align__(128) unsigned g_gen = 0;

// ------------------------------ helpers ------------------------------------
__device__ __forceinline__ float gelu_f(float x) {
    return 0.5f * x * (1.0f + erff(x * 0.70710678118654752f));
}
__device__ __forceinline__ float gelu_grad(float x) {
    float cdf = 0.5f * (1.0f + erff(x * 0.70710678118654752f));
    float pdf = 0.3989422804014327f * expf(-0.5f * x * x);
    return cdf + x * pdf;
}
__device__ __forceinline__ float to_tf32(float x) {
    uint32_t u;
    asm("cvt.rna.tf32.f32 %0, %1;" : "=r"(u) : "f"(x));
    return __uint_as_float(u);
}
__device__ __forceinline__ void mma_tf32(float (&c)[4], const uint32_t (&a)[4],
                                         const uint32_t (&b)[2]) {
    asm volatile(
        "mma.sync.aligned.m16n8k8.row.col.f32.tf32.tf32.f32 "
        "{%0,%1,%2,%3}, {%4,%5,%6,%7}, {%8,%9}, {%0,%1,%2,%3};"
        : "+f"(c[0]), "+f"(c[1]), "+f"(c[2]), "+f"(c[3])
        : "r"(a[0]), "r"(a[1]), "r"(a[2]), "r"(a[3]), "r"(b[0]), "r"(b[1]));
}

// Hot-spin grid barrier, bounded (sync bug -> wrong output, not a hang).
__device__ __forceinline__ void grid_sync(unsigned nb) {
    __syncthreads();
    if (threadIdx.x == 0) {
        unsigned gen = *(volatile unsigned*)&g_gen;
        __threadfence();
        if (atomicAdd(&g_cnt, 1) == nb - 1) {
            g_cnt = 0;
            __threadfence();
            atomicAdd(&g_gen, 1);
        } else {
            for (int spin = 0; spin < 1000000; spin++) {
                if (*(volatile unsigned*)&g_gen != gen) break;
            }
        }
        __threadfence();
    }
    __syncthreads();
}

// ---------------------------------------------------------------------------
// Phase A: C[M,N] = A[M,K] @ B[N,K]^T via tf32 mma.sync (unchanged, passing).
// ---------------------------------------------------------------------------
__global__ __launch_bounds__(256, 2) void gemm_nt_tf32(
    const float* __restrict__ A, const float* __restrict__ B,
    float* __restrict__ C, int M, int N, int K)
{
    __shared__ float As[2][16][136];
    __shared__ float Bs[2][16][136];
    const int m0 = blockIdx.x * 128, n0 = blockIdx.y * 128;
    const int tid = threadIdx.x;
    const int lrow = tid & 127, lc8 = (tid >> 7) * 8;
    const int w = tid >> 5, lane = tid & 31;
    const int wm = w >> 2, wn = w & 3;
    const int g = lane >> 2, q = lane & 3;

    float acc[4][4][4] = {};
    const float* Ag = A + (size_t)(m0 + lrow) * K + lc8;
    const float* Bg = B + (size_t)(n0 + lrow) * K + lc8;

    float4 ra0 = *(const float4*)(Ag);
    float4 ra1 = *(const float4*)(Ag + 4);
    float4 rb0 = *(const float4*)(Bg);
    float4 rb1 = *(const float4*)(Bg + 4);

    const int S = K / 16;
    for (int s = 0; s < S; s++) {
        const int buf = s & 1;
        {
            float* pa = &As[buf][lc8][lrow];
            pa[0*136] = to_tf32(ra0.x); pa[1*136] = to_tf32(ra0.y);
            pa[2*136] = to_tf32(ra0.z); pa[3*136] = to_tf32(ra0.w);
            pa[4*136] = to_tf32(ra1.x); pa[5*136] = to_tf32(ra1.y);
            pa[6*136] = to_tf32(ra1.z); pa[7*136] = to_tf32(ra1.w);
            float* pb = &Bs[buf][lc8][lrow];
            pb[0*136] = to_tf32(rb0.x); pb[1*136] = to_tf32(rb0.y);
            pb[2*136] = to_tf32(rb0.z); pb[3*136] = to_tf32(rb0.w);
            pb[4*136] = to_tf32(rb1.x); pb[5*136] = to_tf32(rb1.y);
            pb[6*136] = to_tf32(rb1.z); pb[7*136] = to_tf32(rb1.w);
        }
        if (s + 1 < S) {
            const float* a2 = Ag + (s + 1) * 16;
            const float* b2 = Bg + (s + 1) * 16;
            ra0 = *(const float4*)(a2);     ra1 = *(const float4*)(a2 + 4);
            rb0 = *(const float4*)(b2);     rb1 = *(const float4*)(b2 + 4);
        }
        __syncthreads();
#pragma unroll
        for (int kc = 0; kc < 16; kc += 8) {
            uint32_t af[4][4], bf[4][2];
#pragma unroll
            for (int mt = 0; mt < 4; mt++) {
                int r = wm * 64 + mt * 16 + g;
                af[mt][0] = __float_as_uint(As[buf][kc + q][r]);
                af[mt][1] = __float_as_uint(As[buf][kc + q][r + 8]);
                af[mt][2] = __float_as_uint(As[buf][kc + q + 4][r]);
                af[mt][3] = __float_as_uint(As[buf][kc + q + 4][r + 8]);
            }
#pragma unroll
            for (int nt = 0; nt < 4; nt++) {
                int c = wn * 32 + nt * 8 + g;
                bf[nt][0] = __float_as_uint(Bs[buf][kc + q][c]);
                bf[nt][1] = __float_as_uint(Bs[buf][kc + q + 4][c]);
            }
#pragma unroll
            for (int mt = 0; mt < 4; mt++)
#pragma unroll
                for (int nt = 0; nt < 4; nt++)
                    mma_tf32(acc[mt][nt], af[mt], bf[nt]);
        }
        __syncthreads();
    }
#pragma unroll
    for (int mt = 0; mt < 4; mt++)
#pragma unroll
        for (int nt = 0; nt < 4; nt++) {
            int r = m0 + wm * 64 + mt * 16 + g;
            int c = n0 + wn * 32 + nt * 8 + q * 2;
            *(float2*)&C[(size_t)r * N + c] =
                make_float2(acc[mt][nt][0], acc[mt][nt][1]);
            *(float2*)&C[(size_t)(r + 8) * N + c] =
                make_float2(acc[mt][nt][2], acc[mt][nt][3]);
        }
}

// ---------------------------------------------------------------------------
// K=256 tiles (S10 fp32, R2 tf32, R5 tf32). Entry-guard sync; ONE sync per
// 16-k slab (double-buffered). MODE 0 NT; MODE 2 TN.
// ---------------------------------------------------------------------------
template <int MODE, int TM>
__device__ __forceinline__ void k256_fetch(
    const float* __restrict__ A, const float* __restrict__ B,
    int lda, int ldb, int m0, int n0, int k0, int tid,
    float4& ra, float2& ra2, float4& rb)
{
    if (MODE == 2) {
        ra = *(const float4*)(A + (size_t)(k0 + (tid >> 4)) * lda + m0 + (tid & 15) * 4);
    } else if (TM == 64) {
        ra = *(const float4*)(A + (size_t)(m0 + (tid >> 2)) * lda + k0 + (tid & 3) * 4);
    } else {
        ra2 = *(const float2*)(A + (size_t)(m0 + (tid >> 3)) * lda + k0 + (tid & 7) * 2);
    }
    if (MODE == 0) {
        rb = *(const float4*)(B + (size_t)(n0 + (tid >> 2)) * ldb + k0 + (tid & 3) * 4);
    } else {
        rb = *(const float4*)(B + (size_t)(k0 + (tid >> 4)) * ldb + n0 + (tid & 15) * 4);
    }
}

template <int MODE, int TM>
__device__ __forceinline__ void k256_store(
    float* dA, float* dB, int tid,
    const float4& ra, const float2& ra2, const float4& rb)
{
    if (MODE == 2) {
        *(float4*)(dA + (tid >> 4) * SL + (tid & 15) * 4) = ra;
    } else if (TM == 64) {
        int r = tid >> 2, c = (tid & 3) * 4;
        dA[(c + 0) * SL + r] = ra.x; dA[(c + 1) * SL + r] = ra.y;
        dA[(c + 2) * SL + r] = ra.z; dA[(c + 3) * SL + r] = ra.w;
    } else {
        int r = tid >> 3, c = (tid & 7) * 2;
        dA[(c + 0) * SL + r] = ra2.x; dA[(c + 1) * SL + r] = ra2.y;
    }
    if (MODE == 0) {
        int r = tid >> 2, c = (tid & 3) * 4;
        dB[(c + 0) * SL + r] = rb.x; dB[(c + 1) * SL + r] = rb.y;
        dB[(c + 2) * SL + r] = rb.z; dB[(c + 3) * SL + r] = rb.w;
    } else {
        *(float4*)(dB + (tid >> 4) * SL + (tid & 15) * 4) = rb;
    }
}

// fp32 SIMT 32x64 tile (exact; S10 output path). 2x4 microtile.
__device__ __forceinline__ void tile_f32_s10(
    const float* __restrict__ A, const float* __restrict__ B, float* sm,
    int m0, int n0, float (&acc)[2][4])
{
    const int tid = threadIdx.x;
    const int tx = tid & 15, ty = tid >> 4;
    float* smA = sm;
    float* smB = sm + 2 * SLAB;
    float4 ra, rb; float2 ra2;

    k256_fetch<0, 32>(A, B, H4, H4, m0, n0, 0, tid, ra, ra2, rb);
    __syncthreads();
    for (int s = 0; s < 16; s++) {
        const int buf = s & 1;
        k256_store<0, 32>(smA + buf * SLAB, smB + buf * SLAB, tid, ra, ra2, rb);
        if (s + 1 < 16)
            k256_fetch<0, 32>(A, B, H4, H4, m0, n0, (s + 1) * 16, tid, ra, ra2, rb);
        __syncthreads();
        const float* cA = smA + buf * SLAB;
        const float* cB = smB + buf * SLAB;
#pragma unroll
        for (int k = 0; k < 16; k++) {
            float4 b = *(const float4*)(cB + k * SL + tx * 4);
            float2 a = *(const float2*)(cA + k * SL + ty * 2);
#pragma unroll
            for (int j = 0; j < 4; j++) {
                float bj = (&b.x)[j];
                acc[0][j] += a.x * bj; acc[1][j] += a.y * bj;
            }
        }
    }
}

// tf32 mma tile for K=256 regions (R2 32x64 NT, R5 64x64 TN).
template <int MODE, int TM>
__device__ __forceinline__ void tile_mma_k256(
    const float* __restrict__ A, const float* __restrict__ B, float* sm,
    int lda, int ldb, int m0, int n0, int Kn,
    float (&acc)[TM / 32][2][4])
{
    const int tid = threadIdx.x;
    const int w = tid >> 5, lane = tid & 31;
    const int wm = w >> 2, wn = w & 3;
    const int g = lane >> 2, q = lane & 3;
    float* smA = sm;
    float* smB = sm + 2 * SLAB;
    const int nslab = Kn >> 4;
    float4 ra, rb; float2 ra2;

    k256_fetch<MODE, TM>(A, B, lda, ldb, m0, n0, 0, tid, ra, ra2, rb);
    __syncthreads();
    for (int s = 0; s < nslab; s++) {
        const int buf = s & 1;
        k256_store<MODE, TM>(smA + buf * SLAB, smB + buf * SLAB, tid, ra, ra2, rb);
        if (s + 1 < nslab)
            k256_fetch<MODE, TM>(A, B, lda, ldb, m0, n0, (s + 1) * 16, tid, ra, ra2, rb);
        __syncthreads();
        const float* cA = smA + buf * SLAB;
        const float* cB = smB + buf * SLAB;
#pragma unroll
        for (int kc = 0; kc < 16; kc += 8) {
            uint32_t af[TM / 32][4], bf[2][2];
#pragma unroll
            for (int mt = 0; mt < TM / 32; mt++) {
                int r = wm * (TM / 2) + mt * 16 + g;
                af[mt][0] = __float_as_uint(cA[(kc + q) * SL + r]);
                af[mt][1] = __float_as_uint(cA[(kc + q) * SL + r + 8]);
                af[mt][2] = __float_as_uint(cA[(kc + q + 4) * SL + r]);
                af[mt][3] = __float_as_uint(cA[(kc + q + 4) * SL + r + 8]);
            }
#pragma unroll
            for (int nt = 0; nt < 2; nt++) {
                int c = wn * 16 + nt * 8 + g;
                bf[nt][0] = __float_as_uint(cB[(kc + q) * SL + c]);
                bf[nt][1] = __float_as_uint(cB[(kc + q + 4) * SL + c]);
            }
#pragma unroll
            for (int mt = 0; mt < TM / 32; mt++)
#pragma unroll
                for (int nt = 0; nt < 2; nt++)
                    mma_tf32(acc[mt][nt], af[mt], bf[nt]);
        }
    }
}

// ---------------------------------------------------------------------------
// Fused full-K tile: 16x32 output, K=1024 split across 2 warp-groups
// (warps 0-3: K[0:512), warps 4-7: K[512:1024)), 32-k slabs, double-buffered,
// ONE sync per slab. Cross-group reduce via smem; after return GROUP-0 warps
// hold complete C fragments (m16n8 per warp wn).
// MODE 0 NT: A[m,k],B[n,k]; MODE 1 NN: A[m,k],B[k,n].
// SPLIT 0: plain tf32; 1: 3-mma split-tf32 (near-fp32).
// smem floats: As [2grp][2buf][32k][17] = 2176 at 0
//              Bs [2grp][2buf][32k][33] = 4224 at 2176
//              RED 512 at 6400. Total 6912 <= 7168.
// ---------------------------------------------------------------------------
template <int MODE, int SPLIT>
__device__ __forceinline__ void tile_fullk(
    const float* __restrict__ A, const float* __restrict__ B, float* sm,
    int lda, int ldb, int m0, int n0, int K, float (&acc)[4])
{
    const int tid = threadIdx.x;
    const int w = tid >> 5, lane = tid & 31;
    const int grp = tid >> 7;
    const int wn = w & 3;
    const int g = lane >> 2, q = lane & 3;
    const int Kh = K >> 1;
    const int nslab = Kh >> 5;
    const int kbase = grp * Kh;

    float* myA = sm + grp * 1088;
    float* myB = sm + 2176 + grp * 2112;
    float* RED = sm + 6400;

    const int st = tid & 127;
    const int am = st >> 3, ak = (st & 7) * 4;       // A: 16m x 32k
    const int bn = st >> 2, bk = (st & 3) * 4;       // B NT: 32n x 32k
    const int bk2 = st >> 3, bn2 = (st & 7) * 4;     // B NN: 32k x 32n

    float4 ra, rb0, rb1;
    // prologue fetch: slab 0
    ra = *(const float4*)(A + (size_t)(m0 + am) * lda + kbase + ak);
    if (MODE == 0) {
        const float* bp = B + (size_t)(n0 + bn) * ldb + kbase + bk;
        rb0 = *(const float4*)(bp);
        rb1 = *(const float4*)(bp + 16);
    } else {
        rb0 = *(const float4*)(B + (size_t)(kbase + bk2) * ldb + n0 + bn2);
        rb1 = *(const float4*)(B + (size_t)(kbase + bk2 + 16) * ldb + n0 + bn2);
    }

    __syncthreads();                       // guard: prior tile smem reads done
    for (int s = 0; s < nslab; s++) {
        const int buf = s & 1;
        {
            float* dA = myA + buf * 544;
            float* dB = myB + buf * 1056;
            dA[(ak + 0) * 17 + am] = ra.x; dA[(ak + 1) * 17 + am] = ra.y;
            dA[(ak + 2) * 17 + am] = ra.z; dA[(ak + 3) * 17 + am] = ra.w;
            if (MODE == 0) {
                dB[(bk + 0) * 33 + bn] = rb0.x; dB[(bk + 1) * 33 + bn] = rb0.y;
                dB[(bk + 2) * 33 + bn] = rb0.z; dB[(bk + 3) * 33 + bn] = rb0.w;
                dB[(bk + 16) * 33 + bn] = rb1.x; dB[(bk + 17) * 33 + bn] = rb1.y;
                dB[(bk + 18) * 33 + bn] = rb1.z; dB[(bk + 19) * 33 + bn] = rb1.w;
            } else {
                dB[bk2 * 33 + bn2 + 0] = rb0.x; dB[bk2 * 33 + bn2 + 1] = rb0.y;
                dB[bk2 * 33 + bn2 + 2] = rb0.z; dB[bk2 * 33 + bn2 + 3] = rb0.w;
                dB[(bk2 + 16) * 33 + bn2 + 0] = rb1.x;
                dB[(bk2 + 16) * 33 + bn2 + 1] = rb1.y;
                dB[(bk2 + 16) * 33 + bn2 + 2] = rb1.z;
                dB[(bk2 + 16) * 33 + bn2 + 3] = rb1.w;
            }
        }
        if (s + 1 < nslab) {
            int ks = kbase + (s + 1) * 32;
            ra = *(const float4*)(A + (size_t)(m0 + am) * lda + ks + ak);
            if (MODE == 0) {
                const float* bp = B + (size_t)(n0 + bn) * ldb + ks + bk;
                rb0 = *(const float4*)(bp);
                rb1 = *(const float4*)(bp + 16);
            } else {
                rb0 = *(const float4*)(B + (size_t)(ks + bk2) * ldb + n0 + bn2);
                rb1 = *(const float4*)(B + (size_t)(ks + bk2 + 16) * ldb + n0 + bn2);
            }
        }
        __syncthreads();
        const float* cA = myA + buf * 544;
        const float* cB = myB + buf * 1056;
#pragma unroll
        for (int kc = 0; kc < 32; kc += 8) {
            float a0 = cA[(kc + q) * 17 + g];
            float a1 = cA[(kc + q) * 17 + g + 8];
            float a2 = cA[(kc + q + 4) * 17 + g];
            float a3 = cA[(kc + q + 4) * 17 + g + 8];
            int c = wn * 8 + g;
            float b0 = cB[(kc + q) * 33 + c];
            float b1 = cB[(kc + q + 4) * 33 + c];
            if (SPLIT == 0) {
                uint32_t af[4] = {__float_as_uint(a0), __float_as_uint(a1),
                                  __float_as_uint(a2), __float_as_uint(a3)};
                uint32_t bf[2] = {__float_as_uint(b0), __float_as_uint(b1)};
                mma_tf32(acc, af, bf);
            } else {
                float ah0 = to_tf32(a0), ah1 = to_tf32(a1);
                float ah2 = to_tf32(a2), ah3 = to_tf32(a3);
                float bh0 = to_tf32(b0), bh1 = to_tf32(b1);
                uint32_t afh[4] = {__float_as_uint(ah0), __float_as_uint(ah1),
                                   __float_as_uint(ah2), __float_as_uint(ah3)};
                uint32_t bfh[2] = {__float_as_uint(bh0), __float_as_uint(bh1)};
                mma_tf32(acc, afh, bfh);
                uint32_t afl[4] = {__float_as_uint(to_tf32(a0 - ah0)),
                                   __float_as_uint(to_tf32(a1 - ah1)),
                                   __float_as_uint(to_tf32(a2 - ah2)),
                                   __float_as_uint(to_tf32(a3 - ah3))};
                mma_tf32(acc, afl, bfh);
                uint32_t bfl[2] = {__float_as_uint(to_tf32(b0 - bh0)),
                                   __float_as_uint(to_tf32(b1 - bh1))};
                mma_tf32(acc, afh, bfl);
            }
        }
    }
    // cross-group reduce into group 0 (RED disjoint from As/Bs)
    if (grp == 1)
        *(float4*)(RED + (wn * 32 + lane) * 4) =
            make_float4(acc[0], acc[1], acc[2], acc[3]);
    __syncthreads();
    if (grp == 0) {
        float4 o = *(const float4*)(RED + (wn * 32 + lane) * 4);
        acc[0] += o.x; acc[1] += o.y; acc[2] += o.z; acc[3] += o.w;
    }
}

// ---------------------------------------------------------------------------
// Persistent Phase B kernel: 256 threads/block, one tile-unit per block/wave.
// Regions: R0 (S10 + fused S1'), R2 (dr), R3' (fused da), R5 (updates),
// R6' (fused h2). 5 grid barriers per step.
// ---------------------------------------------------------------------------
__global__ __launch_bounds__(256, 1) void ttt_persistent(float* __restrict__ out,
                                                         int nb)
{
    __shared__ __align__(16) float SM[7168];
    const int bid = blockIdx.x, tid = threadIdx.x;
    const int tx = tid & 15, ty = tid >> 4;
    const int w = tid >> 5, lane = tid & 31;
    const int grp = tid >> 7, wm = w >> 2, wn = w & 3;
    const int g = lane >> 2, q = lane & 3;
    const int gw = (bid * 256 + tid) >> 5;

    for (int step = 0; step <= T_; step++) {
        // ---- R0: S10 of step-1 (fp32, 128 u, 32x64, K=256)
        //        + S1' of step (fused tf32, 128 u, 16x32, K=1024) ----
        {
            const int nA = (step > 0) ? 128 : 0;
            const int nTot = nA + ((step < T_) ? 128 : 0);
            for (int u = bid; u < nTot; u += nb) {
                const int uu = (step > 0) ? u : u + 128;
                if (uu < 128) {
                    const int t = step - 1;
                    const float* Qt = g_Q + (size_t)t * NH;
                    float* od = out + (size_t)t * NH;
                    int m0 = (uu & 7) * 32, n0 = (uu >> 3) * 64;
                    float acc[2][4] = {};
                    tile_f32_s10(g_h2, g_W2, SM, m0, n0, acc);
                    int n = n0 + tx * 4;
                    float4 bb = *(const float4*)(g_b2 + n);
#pragma unroll
                    for (int r = 0; r < 2; r++) {
                        int m = m0 + ty * 2 + r;
                        float4 qv = *(const float4*)(Qt + (size_t)m * HH + n);
                        *(float4*)(od + (size_t)m * HH + n) = make_float4(
                            qv.x + acc[r][0] + bb.x, qv.y + acc[r][1] + bb.y,
                            qv.z + acc[r][2] + bb.z, qv.w + acc[r][3] + bb.w);
                    }
                } else {
                    // S1': a = Zt@W1^T + b1; h = gelu(a)
                    const int v = uu - 128;
                    const float* Zt = g_Z + (size_t)step * NH;
                    int m0 = (v & 15) * 16, n0 = (v >> 4) * 32;
                    float acc[4] = {};
                    tile_fullk<0, 0>(Zt, g_W1, SM, DD, DD, m0, n0, DD, acc);
                    if (grp == 0) {
                        int n = n0 + wn * 8 + q * 2;
                        int m = m0 + g;
                        float2 bb = *(const float2*)(g_b1 + n);
                        float s0 = acc[0] + bb.x, s1 = acc[1] + bb.y;
                        *(float2*)(g_a + (size_t)m * H4 + n) = make_float2(s0, s1);
                        *(float2*)(g_h + (size_t)m * H4 + n) =
                            make_float2(gelu_f(s0), gelu_f(s1));
                        float s2 = acc[2] + bb.x, s3 = acc[3] + bb.y;
                        *(float2*)(g_a + (size_t)(m + 8) * H4 + n) = make_float2(s2, s3);
                        *(float2*)(g_h + (size_t)(m + 8) * H4 + n) =
                            make_float2(gelu_f(s2), gelu_f(s3));
                    }
                }
            }
        }
        grid_sync(nb);
        if (step == T_) break;

        const int t = step;
        const float* Zt = g_Z + (size_t)t * NH;
        const float* Yt = g_Y + (size_t)t * NH;
        const float* Qt = g_Q + (size_t)t * NH;

        // ---- R2: dr = C2*(Zt + h@W2^T + b2 - Yt) (tf32, 128 u, 32x64) ----
        for (int u = bid; u < 128; u += nb) {
            int m0 = (u & 7) * 32, n0 = (u >> 3) * 64;
            float acc[1][2][4] = {};
            tile_mma_k256<0, 32>(g_h, g_W2, SM, H4, H4, m0, n0, H4, acc);
#pragma unroll
            for (int nt = 0; nt < 2; nt++) {
                int m = m0 + wm * 16 + g;
                int nn = n0 + wn * 16 + nt * 8 + q * 2;
                float2 bb = *(const float2*)(g_b2 + nn);
                {
                    float2 zz = *(const float2*)(Zt + (size_t)m * HH + nn);
                    float2 yy = *(const float2*)(Yt + (size_t)m * HH + nn);
                    *(float2*)(g_dr + (size_t)m * HH + nn) = make_float2(
                        C2 * (zz.x + acc[0][nt][0] + bb.x - yy.x),
                        C2 * (zz.y + acc[0][nt][1] + bb.y - yy.y));
                }
                {
                    int m8 = m + 8;
                    float2 zz = *(const float2*)(Zt + (size_t)m8 * HH + nn);
                    float2 yy = *(const float2*)(Yt + (size_t)m8 * HH + nn);
                    *(float2*)(g_dr + (size_t)m8 * HH + nn) = make_float2(
                        C2 * (zz.x + acc[0][nt][2] + bb.x - yy.x),
                        C2 * (zz.y + acc[0][nt][3] + bb.y - yy.y));
                }
            }
        }
        grid_sync(nb);

        // ---- R3': da = (dr @ W2) * gelu'(a) (fused tf32 NN, 128 u, K=1024) ----
        for (int u = bid; u < 128; u += nb) {
            int m0 = (u & 15) * 16, n0 = (u >> 4) * 32;
            float acc[4] = {};
            tile_fullk<1, 0>(g_dr, g_W2, SM, HH, H4, m0, n0, HH, acc);
            if (grp == 0) {
                int n = n0 + wn * 8 + q * 2;
                int m = m0 + g;
                float2 av = *(const float2*)(g_a + (size_t)m * H4 + n);
                *(float2*)(g_da + (size_t)m * H4 + n) = make_float2(
                    acc[0] * gelu_grad(av.x), acc[1] * gelu_grad(av.y));
                float2 av8 = *(const float2*)(g_a + (size_t)(m + 8) * H4 + n);
                *(float2*)(g_da + (size_t)(m + 8) * H4 + n) = make_float2(
                    acc[2] * gelu_grad(av8.x), acc[3] * gelu_grad(av8.y));
            }
        }
        grid_sync(nb);

        // ---- R5: weight updates (tf32 TN, 128 u, Kn=256) + biases ----
        for (int u = bid; u < 128; u += nb) {
            if (u < 64) {
                int i0 = (u & 15) * 64, j0 = (u >> 4) * 64;
                float acc[2][2][4] = {};
                tile_mma_k256<2, 64>(g_dr, g_h, SM, HH, H4, i0, j0, NB, acc);
#pragma unroll
                for (int mt = 0; mt < 2; mt++)
#pragma unroll
                    for (int nt = 0; nt < 2; nt++) {
                        int i = i0 + wm * 32 + mt * 16 + g;
                        int j = j0 + wn * 16 + nt * 8 + q * 2;
                        float2* p0 = (float2*)(g_W2 + (size_t)i * H4 + j);
                        float2 o0 = *p0;
                        o0.x -= LR * acc[mt][nt][0]; o0.y -= LR * acc[mt][nt][1];
                        *p0 = o0;
                        float2* p1 = (float2*)(g_W2 + (size_t)(i + 8) * H4 + j);
                        float2 o1 = *p1;
                        o1.x -= LR * acc[mt][nt][2]; o1.y -= LR * acc[mt][nt][3];
                        *p1 = o1;
                    }
            } else {
                int v = u - 64;
                int j0 = (v & 3) * 64, i0 = (v >> 2) * 64;
                float acc[2][2][4] = {};
                tile_mma_k256<2, 64>(g_da, Zt, SM, H4, DD, j0, i0, NB, acc);
#pragma unroll
                for (int mt = 0; mt < 2; mt++)
#pragma unroll
                    for (int nt = 0; nt < 2; nt++) {
                        int j = j0 + wm * 32 + mt * 16 + g;
                        int i = i0 + wn * 16 + nt * 8 + q * 2;
                        float2* p0 = (float2*)(g_W1 + (size_t)j * DD + i);
                        float2 o0 = *p0;
                        o0.x -= LR * acc[mt][nt][0]; o0.y -= LR * acc[mt][nt][1];
                        *p0 = o0;
                        float2* p1 = (float2*)(g_W1 + (size_t)(j + 8) * DD + i);
                        float2 o1 = *p1;
                        o1.x -= LR * acc[mt][nt][2]; o1.y -= LR * acc[mt][nt][3];
                        *p1 = o1;
                    }
            }
        }
        // bias colsums (warp-parallel, no intra-block syncs)
        for (int c = gw; c < HH; c += nb * 8) {
            float s = 0.f;
            for (int n = lane; n < NB; n += 32) s += g_dr[(size_t)n * HH + c];
#pragma unroll
            for (int o = 16; o > 0; o >>= 1) s += __shfl_xor_sync(0xffffffffu, s, o);
            if (lane == 0) g_b2[c] -= LR * s;
        }
        for (int c = gw; c < H4; c += nb * 8) {
            float s = 0.f;
            for (int n = lane; n < NB; n += 32) s += g_da[(size_t)n * H4 + c];
#pragma unroll
            for (int o = 16; o > 0; o >>= 1) s += __shfl_xor_sync(0xffffffffu, s, o);
            if (lane == 0) g_b1[c] -= LR * s;
        }
        grid_sync(nb);

        // ---- R6': h2 = gelu(Qt@W1_new^T + b1_new) (split-tf32, near-fp32) ----
        for (int u = bid; u < 128; u += nb) {
            int m0 = (u & 15) * 16, n0 = (u >> 4) * 32;
            float acc[4] = {};
            tile_fullk<0, 1>(Qt, g_W1, SM, DD, DD, m0, n0, DD, acc);
            if (grp == 0) {
                int n = n0 + wn * 8 + q * 2;
                int m = m0 + g;
                float2 bb = *(const float2*)(g_b1 + n);
                *(float2*)(g_h2 + (size_t)m * H4 + n) = make_float2(
                    gelu_f(acc[0] + bb.x), gelu_f(acc[1] + bb.y));
                *(float2*)(g_h2 + (size_t)(m + 8) * H4 + n) = make_float2(
                    gelu_f(acc[2] + bb.x), gelu_f(acc[3] + bb.y));
            }
        }
        grid_sync(nb);
    }
}

// ---------------------------------------------------------------------------
// kernel_launch
// ---------------------------------------------------------------------------
extern "C" void kernel_launch(void* const* d_in, const int* in_sizes, int n_in,
                              void* d_out, int out_size)
{
    (void)in_sizes; (void)n_in; (void)out_size;
    const float* in_seq = (const float*)d_in[0];
    const float* t_k = (const float*)d_in[1];
    const float* t_v = (const float*)d_in[2];
    const float* t_q = (const float*)d_in[3];

    float *Z, *Y, *Q, *W1, *b1, *W2, *b2;
    cudaGetSymbolAddress((void**)&Z, g_Z);
    cudaGetSymbolAddress((void**)&Y, g_Y);
    cudaGetSymbolAddress((void**)&Q, g_Q);
    cudaGetSymbolAddress((void**)&W1, g_W1);
    cudaGetSymbolAddress((void**)&b1, g_b1);
    cudaGetSymbolAddress((void**)&W2, g_W2);
    cudaGetSymbolAddress((void**)&b2, g_b2);

    cudaMemcpyAsync(W1, d_in[4], sizeof(float) * H4 * HH, cudaMemcpyDeviceToDevice, 0);
    cudaMemcpyAsync(b1, d_in[5], sizeof(float) * H4, cudaMemcpyDeviceToDevice, 0);
    cudaMemcpyAsync(W2, d_in[6], sizeof(float) * HH * H4, cudaMemcpyDeviceToDevice, 0);
    cudaMemcpyAsync(b2, d_in[7], sizeof(float) * HH, cudaMemcpyDeviceToDevice, 0);

    // Phase A: tf32 tensor-core GEMMs
    const int M_big = T_ * NB;
    dim3 gA(M_big / 128, HH / 128);
    gemm_nt_tf32<<<gA, 256>>>(in_seq, t_k, Z, M_big, HH, DD);
    gemm_nt_tf32<<<gA, 256>>>(in_seq, t_v, Y, M_big, HH, DD);
    gemm_nt_tf32<<<gA, 256>>>(in_seq, t_q, Q, M_big, HH, DD);

    // Phase B: one persistent kernel, exactly one block per SM.
    int sms = 0;
    cudaDeviceGetAttribute(&sms, cudaDevAttrMultiProcessorCount, 0);
    if (sms <= 0 || sms > 148) sms = 148;
    ttt_persistent<<<sms, 256>>>((float*)d_out, sms);
}